// round 16
// baseline (speedup 1.0000x reference)
#include <cuda_runtime.h>
#include <cuda_fp16.h>
#include <cstdint>
#include <cstddef>

// Problem constants
#define S_LEN   2048
#define BATCH   4
#define DMODEL  1024
#define NHEAD   16
#define DK      64
#define ROWS    (S_LEN * BATCH)      // 8192 token rows
#define NTILES  (S_LEN / 64)         // 32 k-tiles in attention

// Q projection scale: (1/sqrt(DK)) * log2(e), so scores land in log2 domain
#define QSCALE 0.18033688011112042f

// ---------------------------------------------------------------------------
// Scratch (device globals; no runtime allocation allowed)
// ---------------------------------------------------------------------------
__device__ __half g_qh[(size_t)ROWS * DMODEL], g_ql[(size_t)ROWS * DMODEL];
__device__ __half g_kh[(size_t)ROWS * DMODEL], g_kl[(size_t)ROWS * DMODEL];
__device__ __half g_vh[(size_t)ROWS * DMODEL], g_vl[(size_t)ROWS * DMODEL];
__device__ __half g_wqkh[(size_t)2 * DMODEL * DMODEL], g_wqkl[(size_t)2 * DMODEL * DMODEL];
__device__ __half g_wvh [(size_t)DMODEL * DMODEL],     g_wvl [(size_t)DMODEL * DMODEL];
__device__ __half g_woth[(size_t)DMODEL * DMODEL],     g_wotl[(size_t)DMODEL * DMODEL];
__device__ __half g_Qh[(size_t)ROWS * DMODEL];
__device__ __half g_Kh[(size_t)ROWS * DMODEL];
__device__ __half g_Vh[(size_t)ROWS * DMODEL];
__device__ __half g_Ch[(size_t)ROWS * DMODEL], g_Cl[(size_t)ROWS * DMODEL];
__device__ float  g_L [(size_t)BATCH * NHEAD * S_LEN];

// ---------------------------------------------------------------------------
// Helpers
// ---------------------------------------------------------------------------
__device__ __forceinline__ void split_h(float x, __half& h, __half& l) {
    h = __float2half_rn(x);
    l = __float2half_rn(x - __half2float(h));
}
__device__ __forceinline__ void mma_f16(
    float& c0, float& c1, float& c2, float& c3,
    uint32_t a0, uint32_t a1, uint32_t a2, uint32_t a3,
    uint32_t b0, uint32_t b1)
{
    asm volatile(
        "mma.sync.aligned.m16n8k16.row.col.f32.f16.f16.f32 "
        "{%0,%1,%2,%3}, {%4,%5,%6,%7}, {%8,%9}, {%0,%1,%2,%3};"
        : "+f"(c0), "+f"(c1), "+f"(c2), "+f"(c3)
        : "r"(a0), "r"(a1), "r"(a2), "r"(a3), "r"(b0), "r"(b1));
}
__device__ __forceinline__ void mma4(float* c, const uint32_t* a,
                                     uint32_t b0, uint32_t b1) {
    mma_f16(c[0], c[1], c[2], c[3], a[0], a[1], a[2], a[3], b0, b1);
}
__device__ __forceinline__ uint32_t s2u(const void* p) {
    return (uint32_t)__cvta_generic_to_shared(p);
}
__device__ __forceinline__ void ldm_x4(uint32_t* r, uint32_t addr) {
    asm volatile("ldmatrix.sync.aligned.m8n8.x4.shared.b16 {%0,%1,%2,%3}, [%4];"
                 : "=r"(r[0]), "=r"(r[1]), "=r"(r[2]), "=r"(r[3]) : "r"(addr));
}
__device__ __forceinline__ void cp16(uint32_t dst, const void* src) {
    asm volatile("cp.async.cg.shared.global [%0], [%1], 16;"
                 :: "r"(dst), "l"(src) : "memory");
}
#define CPC() asm volatile("cp.async.commit_group;" ::: "memory")
#define CPW0() asm volatile("cp.async.wait_group 0;" ::: "memory")
__device__ __forceinline__ float ex2f(float x) {
    float r; asm("ex2.approx.f32 %0, %1;" : "=f"(r) : "f"(x)); return r;
}
__device__ __forceinline__ uint32_t pkh2(float lo, float hi) {
    uint32_t r;
    asm("cvt.rn.f16x2.f32 %0, %1, %2;" : "=r"(r) : "f"(hi), "f"(lo));
    return r;
}

// ---------------------------------------------------------------------------
// Elementwise split for q/k/v (z-selected): fp32 -> (hi, lo) fp16.
// ---------------------------------------------------------------------------
__global__ __launch_bounds__(256) void split3(
    const float* __restrict__ q, const float* __restrict__ k,
    const float* __restrict__ v,
    __half* __restrict__ qh, __half* __restrict__ ql,
    __half* __restrict__ kh, __half* __restrict__ kl,
    __half* __restrict__ vh, __half* __restrict__ vl, int n4)
{
    const float* s; __half *h, *l;
    if (blockIdx.z == 0)      { s = q; h = qh; l = ql; }
    else if (blockIdx.z == 1) { s = k; h = kh; l = kl; }
    else                      { s = v; h = vh; l = vl; }
    int i = blockIdx.x * 256 + threadIdx.x;
    if (i >= n4) return;
    float4 f = ((const float4*)s)[i];
    __half h0, l0, h1, l1, h2, l2, h3, l3;
    split_h(f.x, h0, l0); split_h(f.y, h1, l1);
    split_h(f.z, h2, l2); split_h(f.w, h3, l3);
    ((__half2*)h)[2 * i]     = __halves2half2(h0, h1);
    ((__half2*)h)[2 * i + 1] = __halves2half2(h2, h3);
    ((__half2*)l)[2 * i]     = __halves2half2(l0, l1);
    ((__half2*)l)[2 * i + 1] = __halves2half2(l2, l3);
}

// Weight splits, z-selected: z=0 -> Wqk (n4a), z=1 -> Wv part of Wvot (n4b).
__global__ __launch_bounds__(256) void split_w(
    const float* __restrict__ wqk, const float* __restrict__ wvot,
    __half* __restrict__ wqkh, __half* __restrict__ wqkl,
    __half* __restrict__ wvh,  __half* __restrict__ wvl,
    int n4a, int n4b)
{
    const float* s; __half *h, *l; int n4;
    if (blockIdx.z == 0) { s = wqk;  h = wqkh; l = wqkl; n4 = n4a; }
    else                 { s = wvot; h = wvh;  l = wvl;  n4 = n4b; }
    int i = blockIdx.x * 256 + threadIdx.x;
    if (i >= n4) return;
    float4 f = ((const float4*)s)[i];
    __half h0, l0, h1, l1, h2, l2, h3, l3;
    split_h(f.x, h0, l0); split_h(f.y, h1, l1);
    split_h(f.z, h2, l2); split_h(f.w, h3, l3);
    ((__half2*)h)[2 * i]     = __halves2half2(h0, h1);
    ((__half2*)h)[2 * i + 1] = __halves2half2(h2, h3);
    ((__half2*)l)[2 * i]     = __halves2half2(l0, l1);
    ((__half2*)l)[2 * i + 1] = __halves2half2(l2, l3);
}

// ---------------------------------------------------------------------------
// Transpose + split Wo2: g_wot{h,l}[e*D + d] = split(Wvot[(D + d)*D + e])
// ---------------------------------------------------------------------------
__global__ void transpose_wo_split(const float* __restrict__ Wvot)
{
    __shared__ float tile[32][33];
    int x = blockIdx.x * 32 + threadIdx.x;   // e
    int y = blockIdx.y * 32 + threadIdx.y;   // d
#pragma unroll
    for (int i = 0; i < 32; i += 8)
        tile[threadIdx.y + i][threadIdx.x] =
            Wvot[(size_t)(DMODEL + y + i) * DMODEL + x];
    __syncthreads();
    int x2 = blockIdx.y * 32 + threadIdx.x;  // d
    int y2 = blockIdx.x * 32 + threadIdx.y;  // e
#pragma unroll
    for (int i = 0; i < 32; i += 8) {
        float v = tile[threadIdx.x][threadIdx.y + i];
        __half h, l; split_h(v, h, l);
        g_woth[(size_t)(y2 + i) * DMODEL + x2] = h;
        g_wotl[(size_t)(y2 + i) * DMODEL + x2] = l;
    }
}

// ---------------------------------------------------------------------------
// Pre-split fp16 NT GEMM body, BK=64, double-buffered (2-stage).
// C[m][n] = sum_k A[m][k] * B[n][k];  2 terms: AhBh + AlBh.
// Block 128x128, 256 thr = 8 warps (4m x 2n), warp tile 32x64.
// smem stride 72 halfs (144 B row pitch -> conflict-free ldmatrix).
// Same k16 MMA order as the BK=32 version => bitwise-identical results.
// ---------------------------------------------------------------------------
#define KST2 72
#define ASZ2H (128 * KST2)          // halfs per array per buffer
#define ASZ2B (ASZ2H * 2)           // bytes (18432)
#define BUF2B (3 * ASZ2B)           // Ah, Al, Bh (55296)

template<bool HOUT>
__device__ __forceinline__ void gemm_body(
    const __half* __restrict__ Ah, const __half* __restrict__ Al,
    const __half* __restrict__ Bh,
    float* __restrict__ Cf, __half* __restrict__ Ch, float scale,
    int M, int N, int K, __half* smem_g, int bm, int bn)
{
    const int tid  = threadIdx.x;
    const int warp = tid >> 5;
    const int lane = tid & 31;
    const int g    = lane >> 2;
    const int tg   = lane & 3;
    const int wm   = (warp >> 1) * 32;
    const int wn   = (warp & 1) * 64;
    const int r8   = lane & 7;
    const int sel  = lane >> 3;

    const int lrow = tid >> 1;                 // 0..127
    const int lcol = (tid & 1) * 32;           // 0 or 32
    const __half* gA_h = Ah + (size_t)(bm + lrow) * K + lcol;
    const __half* gA_l = Al + (size_t)(bm + lrow) * K + lcol;
    const __half* gB_h = Bh + (size_t)(bn + lrow) * K + lcol;
    const uint32_t sbase = s2u(smem_g);
    const uint32_t drowB = (uint32_t)(lrow * KST2 + lcol) * 2;

    float acc[2][8][4] = {};
    const int nIt = K / 64;

#define GEMM_ISSUE(IT, P)                                                     \
    {                                                                         \
        uint32_t d = sbase + (uint32_t)(P) * BUF2B + drowB;                   \
        const __half* s0 = gA_h + (size_t)(IT) * 64;                          \
        cp16(d, s0);      cp16(d + 16, s0 + 8);                               \
        cp16(d + 32, s0 + 16); cp16(d + 48, s0 + 24);                         \
        const __half* s1 = gA_l + (size_t)(IT) * 64;                          \
        cp16(d + ASZ2B, s1);      cp16(d + ASZ2B + 16, s1 + 8);               \
        cp16(d + ASZ2B + 32, s1 + 16); cp16(d + ASZ2B + 48, s1 + 24);         \
        const __half* s2 = gB_h + (size_t)(IT) * 64;                          \
        cp16(d + 2 * ASZ2B, s2);      cp16(d + 2 * ASZ2B + 16, s2 + 8);       \
        cp16(d + 2 * ASZ2B + 32, s2 + 16); cp16(d + 2 * ASZ2B + 48, s2 + 24); \
        CPC();                                                                \
    }

    GEMM_ISSUE(0, 0)

    for (int it = 0; it < nIt; it++) {
        CPW0();
        __syncthreads();
        if (it + 1 < nIt) GEMM_ISSUE(it + 1, (it + 1) & 1)

        const uint32_t cb = sbase + (uint32_t)(it & 1) * BUF2B;
#pragma unroll
        for (int kc = 0; kc < 64; kc += 16) {
            uint32_t ah[2][4], al[2][4];
#pragma unroll
            for (int t = 0; t < 2; t++) {
                const uint32_t ad = cb +
                    (uint32_t)((wm + t * 16 + (sel & 1) * 8 + r8) * KST2
                               + kc + (sel >> 1) * 8) * 2;
                ldm_x4(ah[t], ad);
                ldm_x4(al[t], ad + ASZ2B);
            }
#pragma unroll
            for (int jp = 0; jp < 4; jp++) {
                const uint32_t bd = cb + 2 * ASZ2B +
                    (uint32_t)((wn + jp * 16 + (sel >> 1) * 8 + r8) * KST2
                               + kc + (sel & 1) * 8) * 2;
                uint32_t bh4[4];
                ldm_x4(bh4, bd);
#pragma unroll
                for (int e = 0; e < 2; e++) {
                    const int j = jp * 2 + e;
#pragma unroll
                    for (int t = 0; t < 2; t++) {
                        mma4(acc[t][j], ah[t], bh4[2 * e], bh4[2 * e + 1]);
                        mma4(acc[t][j], al[t], bh4[2 * e], bh4[2 * e + 1]);
                    }
                }
            }
        }
    }
#undef GEMM_ISSUE

#pragma unroll
    for (int t = 0; t < 2; t++)
#pragma unroll
        for (int j = 0; j < 8; j++) {
            const int r0 = bm + wm + t * 16 + g;
            const int cc = bn + wn + j * 8 + 2 * tg;
            float* c = acc[t][j];
            if (HOUT) {
                *(__half2*)&Ch[(size_t)r0 * N + cc] =
                    __floats2half2_rn(c[0] * scale, c[1] * scale);
                *(__half2*)&Ch[(size_t)(r0 + 8) * N + cc] =
                    __floats2half2_rn(c[2] * scale, c[3] * scale);
            } else {
                *(float2*)(Cf + (size_t)r0 * N + cc)       = make_float2(c[0], c[1]);
                *(float2*)(Cf + (size_t)(r0 + 8) * N + cc) = make_float2(c[2], c[3]);
            }
        }
}

__global__ __launch_bounds__(256, 2) void gemm_qkv(
    const __half* __restrict__ qh, const __half* __restrict__ ql,
    const __half* __restrict__ kh, const __half* __restrict__ kl,
    const __half* __restrict__ vh, const __half* __restrict__ vl,
    const __half* __restrict__ wqkh, const __half* __restrict__ wvh,
    __half* __restrict__ Qh, __half* __restrict__ Kh, __half* __restrict__ Vh)
{
    extern __shared__ __align__(16) __half smem_g[];
    const __half *Ah, *Al, *Bh; __half* C; float scale;
    if (blockIdx.z == 0) {
        Ah = qh; Al = ql; Bh = wqkh; C = Qh; scale = QSCALE;
    } else if (blockIdx.z == 1) {
        Ah = kh; Al = kl; Bh = wqkh + (size_t)DMODEL * DMODEL; C = Kh; scale = 1.0f;
    } else {
        Ah = vh; Al = vl; Bh = wvh; C = Vh; scale = 1.0f;
    }
    gemm_body<true>(Ah, Al, Bh, nullptr, C, scale,
                    ROWS, DMODEL, DMODEL, smem_g,
                    blockIdx.y * 128, blockIdx.x * 128);
}

// ---------------------------------------------------------------------------
// Attention, Q-tile 128, cp.async double-buffered K/V, ldmatrix frag loads.
// (proven R12/R13 version, unchanged)
// ---------------------------------------------------------------------------
#define AST 72   // smem stride in halfs

__global__ __launch_bounds__(256, 2) void attn16()
{
    extern __shared__ __align__(16) unsigned char smraw[];
    __half* sQ  = (__half*)smraw;                      // [128][AST]
    __half* sKV = sQ + 128 * AST;                      // [2][128][AST] (K then V)
    __half* sP  = sKV + 2 * 128 * AST;                 // [128][AST]
    float*  psum = (float*)(smraw + (size_t)512 * AST * 2);  // [2][128]
    float*  sL   = psum + 256;                               // [128]

    const int tid  = threadIdx.x;
    const int warp = tid >> 5;
    const int lane = tid & 31;
    const int g    = lane >> 2;
    const int tg   = lane & 3;
    const int r8   = lane & 7;
    const int sel  = lane >> 3;
    const int wm   = (warp >> 1) * 32;     // 0,32,64,96
    const int wn   = (warp & 1) * 32;      // 0,32

    const int bh = blockIdx.y;
    const int b  = bh >> 4;
    const int h  = bh & 15;
    const int q0 = blockIdx.x * 128;

    {
        const int qrow = tid >> 1;
        const int qcol = (tid & 1) * 32;
        const __half* qp = g_Qh + ((size_t)(q0 + qrow) * BATCH + b) * DMODEL + h * DK + qcol;
#pragma unroll
        for (int v = 0; v < 4; v++)
            *(uint4*)&sQ[qrow * AST + qcol + 8 * v] = *(const uint4*)(qp + 8 * v);
    }
    if (tid < 128) sL[tid] = 0.0f;

    const int krow = tid >> 2;             // 0..63
    const int kcol = (tid & 3) * 16;
    const uint32_t kvb = s2u(sKV);
    const uint32_t kvoff = (uint32_t)(krow * AST + kcol) * 2;

#define AT_ISSUE(KT, B)                                                        \
    {                                                                          \
        const uint32_t d = kvb + (uint32_t)(B) * (128 * AST * 2) + kvoff;      \
        const __half* kp = g_Kh + ((size_t)((KT) * 64 + krow) * BATCH + b) * DMODEL + h * DK + kcol; \
        const __half* vp = g_Vh + ((size_t)((KT) * 64 + krow) * BATCH + b) * DMODEL + h * DK + kcol; \
        cp16(d, kp); cp16(d + 16, kp + 8);                                     \
        cp16(d + 64 * AST * 2, vp); cp16(d + 64 * AST * 2 + 16, vp + 8);       \
        CPC();                                                                 \
    }

    AT_ISSUE(0, 0)

    float cctx[2][4][4] = {};

    for (int kt = 0; kt < NTILES; kt++) {
        const int cur = kt & 1;
        __half* sK = sKV + cur * 128 * AST;
        __half* sV = sK + 64 * AST;
        CPW0();
        __syncthreads();
        if (kt + 1 < NTILES) AT_ISSUE(kt + 1, cur ^ 1)

        float cs[2][4][4] = {};
#pragma unroll
        for (int kc = 0; kc < 64; kc += 16) {
            uint32_t aq[2][4];
#pragma unroll
            for (int t = 0; t < 2; t++)
                ldm_x4(aq[t], s2u(&sQ[(wm + t * 16 + (sel & 1) * 8 + r8) * AST
                                      + kc + (sel >> 1) * 8]));
#pragma unroll
            for (int up = 0; up < 2; up++) {
                uint32_t bf[4];
                ldm_x4(bf, s2u(&sK[(wn + up * 16 + (sel >> 1) * 8 + r8) * AST
                                   + kc + (sel & 1) * 8]));
#pragma unroll
                for (int t = 0; t < 2; t++) {
                    mma4(cs[t][2 * up],     aq[t], bf[0], bf[1]);
                    mma4(cs[t][2 * up + 1], aq[t], bf[2], bf[3]);
                }
            }
        }

        uint32_t ph[2][4][2];
#pragma unroll
        for (int t = 0; t < 2; t++) {
#pragma unroll
            for (int u = 0; u < 4; u++)
#pragma unroll
                for (int r = 0; r < 4; r++) cs[t][u][r] = ex2f(cs[t][u][r]);

            float r0 = 0.f, r1 = 0.f;
#pragma unroll
            for (int u = 0; u < 4; u++) {
                r0 += cs[t][u][0] + cs[t][u][1];
                r1 += cs[t][u][2] + cs[t][u][3];
            }
            r0 += __shfl_xor_sync(0xffffffffu, r0, 1);
            r0 += __shfl_xor_sync(0xffffffffu, r0, 2);
            r1 += __shfl_xor_sync(0xffffffffu, r1, 1);
            r1 += __shfl_xor_sync(0xffffffffu, r1, 2);
            if (tg == 0) {
                psum[(warp & 1) * 128 + wm + t * 16 + g]     = r0;
                psum[(warp & 1) * 128 + wm + t * 16 + g + 8] = r1;
            }
#pragma unroll
            for (int u = 0; u < 4; u++) {
                ph[t][u][0] = pkh2(cs[t][u][0], cs[t][u][1]);
                ph[t][u][1] = pkh2(cs[t][u][2], cs[t][u][3]);
                const int col = wn + u * 8 + 2 * tg;
                *(uint32_t*)&sP[(wm + t * 16 + g) * AST + col]     = ph[t][u][0];
                *(uint32_t*)&sP[(wm + t * 16 + g + 8) * AST + col] = ph[t][u][1];
            }
        }

#pragma unroll
        for (int c = 0; c < 2; c++) {
            const int kc = wn + 16 * c;
            uint32_t ap0[2][4];
#pragma unroll
            for (int t = 0; t < 2; t++) {
                ap0[t][0] = ph[t][2 * c][0];
                ap0[t][1] = ph[t][2 * c][1];
                ap0[t][2] = ph[t][2 * c + 1][0];
                ap0[t][3] = ph[t][2 * c + 1][1];
            }
#pragma unroll
            for (int u = 0; u < 4; u++) {
                const int d0 = wn + u * 8;
                const int vrow = kc + r8 + (sel & 1) * 8;
                uint32_t b0, b1;
                asm volatile("ldmatrix.sync.aligned.m8n8.x2.trans.shared.b16 {%0,%1}, [%2];"
                             : "=r"(b0), "=r"(b1) : "r"(s2u(&sV[vrow * AST + d0])));
#pragma unroll
                for (int t = 0; t < 2; t++)
                    mma4(cctx[t][u], ap0[t], b0, b1);
            }
        }
        __syncthreads();

        const int ko = wn ^ 32;
#pragma unroll
        for (int c = 0; c < 2; c++) {
            const int kc = ko + 16 * c;
            uint32_t ap[2][4];
#pragma unroll
            for (int t = 0; t < 2; t++)
                ldm_x4(ap[t], s2u(&sP[(wm + t * 16 + (sel & 1) * 8 + r8) * AST
                                      + kc + (sel >> 1) * 8]));
#pragma unroll
            for (int u = 0; u < 4; u++) {
                const int d0 = wn + u * 8;
                const int vrow = kc + r8 + (sel & 1) * 8;
                uint32_t b0, b1;
                asm volatile("ldmatrix.sync.aligned.m8n8.x2.trans.shared.b16 {%0,%1}, [%2];"
                             : "=r"(b0), "=r"(b1) : "r"(s2u(&sV[vrow * AST + d0])));
#pragma unroll
                for (int t = 0; t < 2; t++)
                    mma4(cctx[t][u], ap[t], b0, b1);
            }
        }

        if (tid < 128)
            sL[tid] += psum[tid] + psum[128 + tid];
    }
#undef AT_ISSUE
    __syncthreads();

#pragma unroll
    for (int t = 0; t < 2; t++) {
        const int r0 = wm + t * 16 + g;
        const float inv0 = 1.0f / sL[r0];
        const float inv1 = 1.0f / sL[r0 + 8];
#pragma unroll
        for (int u = 0; u < 4; u++) {
            const int cc = h * DK + wn + u * 8 + 2 * tg;
            float* c = cctx[t][u];
            float x0 = c[0] * inv0, x1 = c[1] * inv0;
            float x2 = c[2] * inv1, x3 = c[3] * inv1;
            __half h0, l0, h1, l1;
            size_t o0 = ((size_t)(q0 + r0) * BATCH + b) * DMODEL + cc;
            size_t o1 = ((size_t)(q0 + r0 + 8) * BATCH + b) * DMODEL + cc;
            split_h(x0, h0, l0); split_h(x1, h1, l1);
            *(__half2*)&g_Ch[o0] = __halves2half2(h0, h1);
            *(__half2*)&g_Cl[o0] = __halves2half2(l0, l1);
            split_h(x2, h0, l0); split_h(x3, h1, l1);
            *(__half2*)&g_Ch[o1] = __halves2half2(h0, h1);
            *(__half2*)&g_Cl[o1] = __halves2half2(l0, l1);
        }
    }
    if (tid < 128)
        g_L[(size_t)bh * S_LEN + q0 + tid] = sL[tid];
}

// ---------------------------------------------------------------------------
// Fused tail: blocks [0, 512) = output projection, [512, 2560) = attn_avg.
// ---------------------------------------------------------------------------
#define NOUTBLK 512

__global__ __launch_bounds__(256, 2) void tail_fused(
    const __half* __restrict__ Ch2, const __half* __restrict__ Cl2,
    const __half* __restrict__ woth,
    float* __restrict__ out, float* __restrict__ outA)
{
    extern __shared__ __align__(16) unsigned char smraw[];

    if (blockIdx.x < NOUTBLK) {
        const int bx = blockIdx.x & 7;        // n-tile (DMODEL/128 = 8)
        const int by = blockIdx.x >> 3;       // m-tile (ROWS/128 = 64)
        gemm_body<false>(Ch2, Cl2, woth, out, nullptr, 1.0f,
                         ROWS, DMODEL, DMODEL, (__half*)smraw,
                         by * 128, bx * 128);
        return;
    }

    // ---- attn_avg part ----
    __half* sT  = (__half*)smraw;                 // [2][(128+64)][AST]: Q then K
    float* sInv = (float*)(smraw + (size_t)2 * 192 * AST * 2);  // [16][128]

    const int idx  = blockIdx.x - NOUTBLK;
    const int tid  = threadIdx.x;
    const int warp = tid >> 5;
    const int lane = tid & 31;
    const int g    = lane >> 2;
    const int tg   = lane & 3;
    const int r8   = lane & 7;
    const int sel  = lane >> 3;
    const int wm   = (warp >> 1) * 32;
    const int wn   = (warp & 1) * 32;

    const int j0 = (idx & 31) * 64;          // 32 j-tiles
    const int q0 = ((idx >> 5) & 15) * 128;  // 16 q-tiles
    const int b  = idx >> 9;                 // 4 batches

    for (int i = tid; i < NHEAD * 128; i += 256) {
        const int hh = i >> 7, qq = i & 127;
        sInv[i] = 1.0f / (16.0f * g_L[(size_t)(b * NHEAD + hh) * S_LEN + q0 + qq]);
    }

    const int qrow = tid >> 1;             // 0..127
    const int qcol = (tid & 1) * 32;
    const int krow = tid >> 2;             // 0..63
    const int kcol = (tid & 3) * 16;
    const uint32_t tb = s2u(sT);
    const uint32_t qoff = (uint32_t)(qrow * AST + qcol) * 2;
    const uint32_t koff = (uint32_t)((128 + krow) * AST + kcol) * 2;

#define AV_ISSUE(H, B)                                                         \
    {                                                                          \
        const uint32_t base = tb + (uint32_t)(B) * (192 * AST * 2);            \
        const __half* qp = g_Qh + ((size_t)(q0 + qrow) * BATCH + b) * DMODEL + (H) * DK + qcol; \
        cp16(base + qoff, qp);      cp16(base + qoff + 16, qp + 8);            \
        cp16(base + qoff + 32, qp + 16); cp16(base + qoff + 48, qp + 24);      \
        const __half* kp = g_Kh + ((size_t)(j0 + krow) * BATCH + b) * DMODEL + (H) * DK + kcol; \
        cp16(base + koff, kp);      cp16(base + koff + 16, kp + 8);            \
        CPC();                                                                 \
    }

    AV_ISSUE(0, 0)

    float avg[2][4][4] = {};

    for (int h = 0; h < NHEAD; h++) {
        const int cur = h & 1;
        __half* sQ = sT + cur * 192 * AST;
        __half* sK = sQ + 128 * AST;
        CPW0();
        __syncthreads();
        if (h + 1 < NHEAD) AV_ISSUE(h + 1, cur ^ 1)

        float cs[2][4][4] = {};
#pragma unroll
        for (int kc = 0; kc < 64; kc += 16) {
            uint32_t aq[2][4];
#pragma unroll
            for (int t = 0; t < 2; t++)
                ldm_x4(aq[t], s2u(&sQ[(wm + t * 16 + (sel & 1) * 8 + r8) * AST
                                      + kc + (sel >> 1) * 8]));
#pragma unroll
            for (int up = 0; up < 2; up++) {
                uint32_t bf[4];
                ldm_x4(bf, s2u(&sK[(wn + up * 16 + (sel >> 1) * 8 + r8) * AST
                                   + kc + (sel & 1) * 8]));
#pragma unroll
                for (int t = 0; t < 2; t++) {
                    mma4(cs[t][2 * up],     aq[t], bf[0], bf[1]);
                    mma4(cs[t][2 * up + 1], aq[t], bf[2], bf[3]);
                }
            }
        }

#pragma unroll
        for (int t = 0; t < 2; t++) {
            const float inv0 = sInv[h * 128 + wm + t * 16 + g];
            const float inv1 = sInv[h * 128 + wm + t * 16 + g + 8];
#pragma unroll
            for (int u = 0; u < 4; u++) {
                avg[t][u][0] += ex2f(cs[t][u][0]) * inv0;
                avg[t][u][1] += ex2f(cs[t][u][1]) * inv0;
                avg[t][u][2] += ex2f(cs[t][u][2]) * inv1;
                avg[t][u][3] += ex2f(cs[t][u][3]) * inv1;
            }
        }
    }
#undef AV_ISSUE

#pragma unroll
    for (int t = 0; t < 2; t++) {
        const int r0 = q0 + wm + t * 16 + g;
#pragma unroll
        for (int u = 0; u < 4; u++) {
            const int cc = j0 + wn + u * 8 + 2 * tg;
            float* c = avg[t][u];
            *(float2*)(outA + ((size_t)b * S_LEN + r0) * S_LEN + cc) =
                make_float2(c[0], c[1]);
            *(float2*)(outA + ((size_t)b * S_LEN + r0 + 8) * S_LEN + cc) =
                make_float2(c[2], c[3]);
        }
    }
}

// ---------------------------------------------------------------------------
// Launch
// ---------------------------------------------------------------------------
extern "C" void kernel_launch(void* const* d_in, const int* in_sizes, int n_in,
                              void* d_out, int out_size)
{
    (void)in_sizes; (void)n_in; (void)out_size;
    const float* query = (const float*)d_in[0];
    const float* key   = (const float*)d_in[1];
    const float* value = (const float*)d_in[2];
    const float* Wqk   = (const float*)d_in[3];
    const float* Wvot  = (const float*)d_in[4];

    float* out  = (float*)d_out;                              // (S,B,D)
    float* outA = out + (size_t)S_LEN * BATCH * DMODEL;       // (B,S,S)

    __half *qh, *ql, *kh, *kl, *vh, *vl;
    __half *wqkh, *wqkl, *wvh, *wvl, *woth, *wotl;
    __half *Qh, *Kh, *Vh, *pCh, *pCl;
    cudaGetSymbolAddress((void**)&qh,   g_qh);   cudaGetSymbolAddress((void**)&ql,   g_ql);
    cudaGetSymbolAddress((void**)&kh,   g_kh);   cudaGetSymbolAddress((void**)&kl,   g_kl);
    cudaGetSymbolAddress((void**)&vh,   g_vh);   cudaGetSymbolAddress((void**)&vl,   g_vl);
    cudaGetSymbolAddress((void**)&wqkh, g_wqkh); cudaGetSymbolAddress((void**)&wqkl, g_wqkl);
    cudaGetSymbolAddress((void**)&wvh,  g_wvh);  cudaGetSymbolAddress((void**)&wvl,  g_wvl);
    cudaGetSymbolAddress((void**)&woth, g_woth); cudaGetSymbolAddress((void**)&wotl, g_wotl);
    cudaGetSymbolAddress((void**)&Qh,   g_Qh);   cudaGetSymbolAddress((void**)&Kh,   g_Kh);
    cudaGetSymbolAddress((void**)&Vh,   g_Vh);
    cudaGetSymbolAddress((void**)&pCh,  g_Ch);   cudaGetSymbolAddress((void**)&pCl,  g_Cl);

    const int smem_g2 = 2 * BUF2B;                               // 110592 B
    const int smem_at = 512 * AST * 2 + (256 + 128) * 4;         // 75264 B
    const int smem_tl = smem_g2;                                 // max(110592, 63488)
    cudaFuncSetAttribute(gemm_qkv,
                         cudaFuncAttributeMaxDynamicSharedMemorySize, smem_g2);
    cudaFuncSetAttribute(attn16,
                         cudaFuncAttributeMaxDynamicSharedMemorySize, smem_at);
    cudaFuncSetAttribute(tail_fused,
                         cudaFuncAttributeMaxDynamicSharedMemorySize, smem_tl);

    const int n4_act = ROWS * DMODEL / 4;
    const int n4_wqk = 2 * DMODEL * DMODEL / 4;
    const int n4_wv  = DMODEL * DMODEL / 4;

    split3<<<dim3((n4_act + 255) / 256, 1, 3), 256>>>(
        query, key, value, qh, ql, kh, kl, vh, vl, n4_act);
    split_w<<<dim3((n4_wqk + 255) / 256, 1, 2), 256>>>(
        Wqk, Wvot, wqkh, wqkl, wvh, wvl, n4_wqk, n4_wv);
    transpose_wo_split<<<dim3(32, 32), dim3(32, 8)>>>(Wvot);

    gemm_qkv<<<dim3(DMODEL / 128, ROWS / 128, 3), 256, smem_g2>>>(
        qh, ql, kh, kl, vh, vl, wqkh, wvh, Qh, Kh, Vh);

    attn16<<<dim3(S_LEN / 128, BATCH * NHEAD), 256, smem_at>>>();

    tail_fused<<<NOUTBLK + S_LEN / 64 * S_LEN / 128 * BATCH, 256, smem_tl>>>(
        pCh, pCl, woth, out, outA);
}

// round 17
// speedup vs baseline: 1.1037x; 1.1037x over previous
#include <cuda_runtime.h>
#include <cuda_fp16.h>
#include <cstdint>
#include <cstddef>

// Problem constants
#define S_LEN   2048
#define BATCH   4
#define DMODEL  1024
#define NHEAD   16
#define DK      64
#define ROWS    (S_LEN * BATCH)      // 8192 token rows
#define NTILES  (S_LEN / 64)         // 32 k-tiles in attention

// Q projection scale: (1/sqrt(DK)) * log2(e), so scores land in log2 domain
#define QSCALE 0.18033688011112042f

// ---------------------------------------------------------------------------
// Scratch (device globals; no runtime allocation allowed)
// ---------------------------------------------------------------------------
__device__ __half g_qh[(size_t)ROWS * DMODEL], g_ql[(size_t)ROWS * DMODEL];
__device__ __half g_kh[(size_t)ROWS * DMODEL], g_kl[(size_t)ROWS * DMODEL];
__device__ __half g_vh[(size_t)ROWS * DMODEL], g_vl[(size_t)ROWS * DMODEL];
__device__ __half g_wqkh[(size_t)2 * DMODEL * DMODEL], g_wqkl[(size_t)2 * DMODEL * DMODEL];
__device__ __half g_wvh [(size_t)DMODEL * DMODEL],     g_wvl [(size_t)DMODEL * DMODEL];
__device__ __half g_woth[(size_t)DMODEL * DMODEL],     g_wotl[(size_t)DMODEL * DMODEL];
__device__ __half g_Qh[(size_t)ROWS * DMODEL];
__device__ __half g_Kh[(size_t)ROWS * DMODEL];
__device__ __half g_Vh[(size_t)ROWS * DMODEL];
__device__ __half g_Ch[(size_t)ROWS * DMODEL], g_Cl[(size_t)ROWS * DMODEL];
__device__ float  g_L [(size_t)BATCH * NHEAD * S_LEN];

// ---------------------------------------------------------------------------
// Helpers
// ---------------------------------------------------------------------------
__device__ __forceinline__ void split_h(float x, __half& h, __half& l) {
    h = __float2half_rn(x);
    l = __float2half_rn(x - __half2float(h));
}
__device__ __forceinline__ void mma_f16(
    float& c0, float& c1, float& c2, float& c3,
    uint32_t a0, uint32_t a1, uint32_t a2, uint32_t a3,
    uint32_t b0, uint32_t b1)
{
    asm volatile(
        "mma.sync.aligned.m16n8k16.row.col.f32.f16.f16.f32 "
        "{%0,%1,%2,%3}, {%4,%5,%6,%7}, {%8,%9}, {%0,%1,%2,%3};"
        : "+f"(c0), "+f"(c1), "+f"(c2), "+f"(c3)
        : "r"(a0), "r"(a1), "r"(a2), "r"(a3), "r"(b0), "r"(b1));
}
__device__ __forceinline__ void mma4(float* c, const uint32_t* a,
                                     uint32_t b0, uint32_t b1) {
    mma_f16(c[0], c[1], c[2], c[3], a[0], a[1], a[2], a[3], b0, b1);
}
__device__ __forceinline__ uint32_t s2u(const void* p) {
    return (uint32_t)__cvta_generic_to_shared(p);
}
__device__ __forceinline__ void ldm_x4(uint32_t* r, uint32_t addr) {
    asm volatile("ldmatrix.sync.aligned.m8n8.x4.shared.b16 {%0,%1,%2,%3}, [%4];"
                 : "=r"(r[0]), "=r"(r[1]), "=r"(r[2]), "=r"(r[3]) : "r"(addr));
}
__device__ __forceinline__ void cp16(uint32_t dst, const void* src) {
    asm volatile("cp.async.cg.shared.global [%0], [%1], 16;"
                 :: "r"(dst), "l"(src) : "memory");
}
#define CPC() asm volatile("cp.async.commit_group;" ::: "memory")
#define CPW0() asm volatile("cp.async.wait_group 0;" ::: "memory")
__device__ __forceinline__ float ex2f(float x) {
    float r; asm("ex2.approx.f32 %0, %1;" : "=f"(r) : "f"(x)); return r;
}
__device__ __forceinline__ uint32_t pkh2(float lo, float hi) {
    uint32_t r;
    asm("cvt.rn.f16x2.f32 %0, %1, %2;" : "=r"(r) : "f"(hi), "f"(lo));
    return r;
}

// ---------------------------------------------------------------------------
// Elementwise split for q/k/v (z-selected): fp32 -> (hi, lo) fp16.
// ---------------------------------------------------------------------------
__global__ __launch_bounds__(256) void split3(
    const float* __restrict__ q, const float* __restrict__ k,
    const float* __restrict__ v,
    __half* __restrict__ qh, __half* __restrict__ ql,
    __half* __restrict__ kh, __half* __restrict__ kl,
    __half* __restrict__ vh, __half* __restrict__ vl, int n4)
{
    const float* s; __half *h, *l;
    if (blockIdx.z == 0)      { s = q; h = qh; l = ql; }
    else if (blockIdx.z == 1) { s = k; h = kh; l = kl; }
    else                      { s = v; h = vh; l = vl; }
    int i = blockIdx.x * 256 + threadIdx.x;
    if (i >= n4) return;
    float4 f = ((const float4*)s)[i];
    __half h0, l0, h1, l1, h2, l2, h3, l3;
    split_h(f.x, h0, l0); split_h(f.y, h1, l1);
    split_h(f.z, h2, l2); split_h(f.w, h3, l3);
    ((__half2*)h)[2 * i]     = __halves2half2(h0, h1);
    ((__half2*)h)[2 * i + 1] = __halves2half2(h2, h3);
    ((__half2*)l)[2 * i]     = __halves2half2(l0, l1);
    ((__half2*)l)[2 * i + 1] = __halves2half2(l2, l3);
}

// Weight splits, z-selected: z=0 -> Wqk (n4a), z=1 -> Wv part of Wvot (n4b).
__global__ __launch_bounds__(256) void split_w(
    const float* __restrict__ wqk, const float* __restrict__ wvot,
    __half* __restrict__ wqkh, __half* __restrict__ wqkl,
    __half* __restrict__ wvh,  __half* __restrict__ wvl,
    int n4a, int n4b)
{
    const float* s; __half *h, *l; int n4;
    if (blockIdx.z == 0) { s = wqk;  h = wqkh; l = wqkl; n4 = n4a; }
    else                 { s = wvot; h = wvh;  l = wvl;  n4 = n4b; }
    int i = blockIdx.x * 256 + threadIdx.x;
    if (i >= n4) return;
    float4 f = ((const float4*)s)[i];
    __half h0, l0, h1, l1, h2, l2, h3, l3;
    split_h(f.x, h0, l0); split_h(f.y, h1, l1);
    split_h(f.z, h2, l2); split_h(f.w, h3, l3);
    ((__half2*)h)[2 * i]     = __halves2half2(h0, h1);
    ((__half2*)h)[2 * i + 1] = __halves2half2(h2, h3);
    ((__half2*)l)[2 * i]     = __halves2half2(l0, l1);
    ((__half2*)l)[2 * i + 1] = __halves2half2(l2, l3);
}

// ---------------------------------------------------------------------------
// Transpose + split Wo2: g_wot{h,l}[e*D + d] = split(Wvot[(D + d)*D + e])
// ---------------------------------------------------------------------------
__global__ void transpose_wo_split(const float* __restrict__ Wvot)
{
    __shared__ float tile[32][33];
    int x = blockIdx.x * 32 + threadIdx.x;   // e
    int y = blockIdx.y * 32 + threadIdx.y;   // d
#pragma unroll
    for (int i = 0; i < 32; i += 8)
        tile[threadIdx.y + i][threadIdx.x] =
            Wvot[(size_t)(DMODEL + y + i) * DMODEL + x];
    __syncthreads();
    int x2 = blockIdx.y * 32 + threadIdx.x;  // d
    int y2 = blockIdx.x * 32 + threadIdx.y;  // e
#pragma unroll
    for (int i = 0; i < 32; i += 8) {
        float v = tile[threadIdx.x][threadIdx.y + i];
        __half h, l; split_h(v, h, l);
        g_woth[(size_t)(y2 + i) * DMODEL + x2] = h;
        g_wotl[(size_t)(y2 + i) * DMODEL + x2] = l;
    }
}

// ---------------------------------------------------------------------------
// Pre-split fp16 NT GEMM body (R13-proven BK=32, 3-stage structure).
// TERMS=2: AhBh + AlBh.   TERMS=1: AhBh only (plain fp16 GEMM).
// Block 128x128, BK=32, 256 thr = 8 warps (4m x 2n), warp tile 32x64.
// ---------------------------------------------------------------------------
#define KSTH 40
#define ASZH (128 * KSTH)
#define ASZB (ASZH * 2)

template<int TERMS, bool HOUT, int STAGES>
__device__ __forceinline__ void gemm_body(
    const __half* __restrict__ Ah, const __half* __restrict__ Al,
    const __half* __restrict__ Bh,
    float* __restrict__ Cf, __half* __restrict__ Ch, float scale,
    int M, int N, int K, __half* smem_g, int bm, int bn)
{
    const uint32_t BSB = (TERMS + 1) * ASZB;   // bytes per buffer (A[,Al],B)

    const int tid  = threadIdx.x;
    const int warp = tid >> 5;
    const int lane = tid & 31;
    const int g    = lane >> 2;
    const int tg   = lane & 3;
    const int wm   = (warp >> 1) * 32;
    const int wn   = (warp & 1) * 64;
    const int r8   = lane & 7;
    const int sel  = lane >> 3;

    const int lrow = tid >> 1;
    const int lcol = (tid & 1) * 16;
    const __half* gA_h = Ah + (size_t)(bm + lrow) * K + lcol;
    const __half* gA_l = (TERMS == 2) ? (Al + (size_t)(bm + lrow) * K + lcol) : nullptr;
    const __half* gB_h = Bh + (size_t)(bn + lrow) * K + lcol;
    const uint32_t sbase = s2u(smem_g);
    const uint32_t drowB = (uint32_t)(lrow * KSTH + lcol) * 2;

    float acc[2][8][4] = {};
    const int nIt = K / 32;

#define GEMM_ISSUE(IT, P)                                                     \
    {                                                                         \
        uint32_t d = sbase + (uint32_t)(P) * BSB + drowB;                     \
        const __half* s0 = gA_h + (size_t)(IT) * 32;                          \
        cp16(d, s0); cp16(d + 16, s0 + 8);                                    \
        if (TERMS == 2) {                                                     \
            const __half* s1 = gA_l + (size_t)(IT) * 32;                      \
            cp16(d + ASZB, s1); cp16(d + ASZB + 16, s1 + 8);                  \
        }                                                                     \
        const __half* s2 = gB_h + (size_t)(IT) * 32;                          \
        cp16(d + TERMS * ASZB, s2); cp16(d + TERMS * ASZB + 16, s2 + 8);      \
        CPC();                                                                \
    }

    GEMM_ISSUE(0, 0)
    if (STAGES == 3 && nIt > 1) GEMM_ISSUE(1, 1)

    for (int it = 0; it < nIt; it++) {
        if (STAGES == 3) {
            if (it + 1 < nIt)
                asm volatile("cp.async.wait_group 1;" ::: "memory");
            else
                CPW0();
        } else {
            CPW0();
        }
        __syncthreads();
        const int nx = it + STAGES - 1;
        if (nx < nIt) GEMM_ISSUE(nx, nx % STAGES)

        const uint32_t cb = sbase + (uint32_t)(it % STAGES) * BSB;
#pragma unroll
        for (int kc = 0; kc < 32; kc += 16) {
            uint32_t ah[2][4], al[2][4];
#pragma unroll
            for (int t = 0; t < 2; t++) {
                const uint32_t ad = cb +
                    (uint32_t)((wm + t * 16 + (sel & 1) * 8 + r8) * KSTH
                               + kc + (sel >> 1) * 8) * 2;
                ldm_x4(ah[t], ad);
                if (TERMS == 2) ldm_x4(al[t], ad + ASZB);
            }
#pragma unroll
            for (int jp = 0; jp < 4; jp++) {
                const uint32_t bd = cb + TERMS * ASZB +
                    (uint32_t)((wn + jp * 16 + (sel >> 1) * 8 + r8) * KSTH
                               + kc + (sel & 1) * 8) * 2;
                uint32_t bh4[4];
                ldm_x4(bh4, bd);
#pragma unroll
                for (int e = 0; e < 2; e++) {
                    const int j = jp * 2 + e;
#pragma unroll
                    for (int t = 0; t < 2; t++) {
                        mma4(acc[t][j], ah[t], bh4[2 * e], bh4[2 * e + 1]);
                        if (TERMS == 2)
                            mma4(acc[t][j], al[t], bh4[2 * e], bh4[2 * e + 1]);
                    }
                }
            }
        }
    }
#undef GEMM_ISSUE

#pragma unroll
    for (int t = 0; t < 2; t++)
#pragma unroll
        for (int j = 0; j < 8; j++) {
            const int r0 = bm + wm + t * 16 + g;
            const int cc = bn + wn + j * 8 + 2 * tg;
            float* c = acc[t][j];
            if (HOUT) {
                *(__half2*)&Ch[(size_t)r0 * N + cc] =
                    __floats2half2_rn(c[0] * scale, c[1] * scale);
                *(__half2*)&Ch[(size_t)(r0 + 8) * N + cc] =
                    __floats2half2_rn(c[2] * scale, c[3] * scale);
            } else {
                *(float2*)(Cf + (size_t)r0 * N + cc)       = make_float2(c[0], c[1]);
                *(float2*)(Cf + (size_t)(r0 + 8) * N + cc) = make_float2(c[2], c[3]);
            }
        }
}

// Merged QKV projection: blockIdx.z selects Q/K/V. K uses 1-term (fp16 plain).
__global__ __launch_bounds__(256, 2) void gemm_qkv(
    const __half* __restrict__ qh, const __half* __restrict__ ql,
    const __half* __restrict__ kh,
    const __half* __restrict__ vh, const __half* __restrict__ vl,
    const __half* __restrict__ wqkh, const __half* __restrict__ wvh,
    __half* __restrict__ Qh, __half* __restrict__ Kh, __half* __restrict__ Vh)
{
    extern __shared__ __align__(16) __half smem_g[];
    if (blockIdx.z == 0) {
        gemm_body<2, true, 3>(qh, ql, wqkh, nullptr, Qh, QSCALE,
                              ROWS, DMODEL, DMODEL, smem_g,
                              blockIdx.y * 128, blockIdx.x * 128);
    } else if (blockIdx.z == 1) {
        gemm_body<1, true, 3>(kh, nullptr, wqkh + (size_t)DMODEL * DMODEL,
                              nullptr, Kh, 1.0f,
                              ROWS, DMODEL, DMODEL, smem_g,
                              blockIdx.y * 128, blockIdx.x * 128);
    } else {
        gemm_body<2, true, 3>(vh, vl, wvh, nullptr, Vh, 1.0f,
                              ROWS, DMODEL, DMODEL, smem_g,
                              blockIdx.y * 128, blockIdx.x * 128);
    }
}

// ---------------------------------------------------------------------------
// Attention, Q-tile 128, cp.async double-buffered K/V, ldmatrix frag loads.
// (proven R12/R13 version, unchanged)
// ---------------------------------------------------------------------------
#define AST 72   // smem stride in halfs

__global__ __launch_bounds__(256, 2) void attn16()
{
    extern __shared__ __align__(16) unsigned char smraw[];
    __half* sQ  = (__half*)smraw;                      // [128][AST]
    __half* sKV = sQ + 128 * AST;                      // [2][128][AST] (K then V)
    __half* sP  = sKV + 2 * 128 * AST;                 // [128][AST]
    float*  psum = (float*)(smraw + (size_t)512 * AST * 2);  // [2][128]
    float*  sL   = psum + 256;                               // [128]

    const int tid  = threadIdx.x;
    const int warp = tid >> 5;
    const int lane = tid & 31;
    const int g    = lane >> 2;
    const int tg   = lane & 3;
    const int r8   = lane & 7;
    const int sel  = lane >> 3;
    const int wm   = (warp >> 1) * 32;     // 0,32,64,96
    const int wn   = (warp & 1) * 32;      // 0,32

    const int bh = blockIdx.y;
    const int b  = bh >> 4;
    const int h  = bh & 15;
    const int q0 = blockIdx.x * 128;

    {
        const int qrow = tid >> 1;
        const int qcol = (tid & 1) * 32;
        const __half* qp = g_Qh + ((size_t)(q0 + qrow) * BATCH + b) * DMODEL + h * DK + qcol;
#pragma unroll
        for (int v = 0; v < 4; v++)
            *(uint4*)&sQ[qrow * AST + qcol + 8 * v] = *(const uint4*)(qp + 8 * v);
    }
    if (tid < 128) sL[tid] = 0.0f;

    const int krow = tid >> 2;             // 0..63
    const int kcol = (tid & 3) * 16;
    const uint32_t kvb = s2u(sKV);
    const uint32_t kvoff = (uint32_t)(krow * AST + kcol) * 2;

#define AT_ISSUE(KT, B)                                                        \
    {                                                                          \
        const uint32_t d = kvb + (uint32_t)(B) * (128 * AST * 2) + kvoff;      \
        const __half* kp = g_Kh + ((size_t)((KT) * 64 + krow) * BATCH + b) * DMODEL + h * DK + kcol; \
        const __half* vp = g_Vh + ((size_t)((KT) * 64 + krow) * BATCH + b) * DMODEL + h * DK + kcol; \
        cp16(d, kp); cp16(d + 16, kp + 8);                                     \
        cp16(d + 64 * AST * 2, vp); cp16(d + 64 * AST * 2 + 16, vp + 8);       \
        CPC();                                                                 \
    }

    AT_ISSUE(0, 0)

    float cctx[2][4][4] = {};

    for (int kt = 0; kt < NTILES; kt++) {
        const int cur = kt & 1;
        __half* sK = sKV + cur * 128 * AST;
        __half* sV = sK + 64 * AST;
        CPW0();
        __syncthreads();
        if (kt + 1 < NTILES) AT_ISSUE(kt + 1, cur ^ 1)

        float cs[2][4][4] = {};
#pragma unroll
        for (int kc = 0; kc < 64; kc += 16) {
            uint32_t aq[2][4];
#pragma unroll
            for (int t = 0; t < 2; t++)
                ldm_x4(aq[t], s2u(&sQ[(wm + t * 16 + (sel & 1) * 8 + r8) * AST
                                      + kc + (sel >> 1) * 8]));
#pragma unroll
            for (int up = 0; up < 2; up++) {
                uint32_t bf[4];
                ldm_x4(bf, s2u(&sK[(wn + up * 16 + (sel >> 1) * 8 + r8) * AST
                                   + kc + (sel & 1) * 8]));
#pragma unroll
                for (int t = 0; t < 2; t++) {
                    mma4(cs[t][2 * up],     aq[t], bf[0], bf[1]);
                    mma4(cs[t][2 * up + 1], aq[t], bf[2], bf[3]);
                }
            }
        }

        uint32_t ph[2][4][2];
#pragma unroll
        for (int t = 0; t < 2; t++) {
#pragma unroll
            for (int u = 0; u < 4; u++)
#pragma unroll
                for (int r = 0; r < 4; r++) cs[t][u][r] = ex2f(cs[t][u][r]);

            float r0 = 0.f, r1 = 0.f;
#pragma unroll
            for (int u = 0; u < 4; u++) {
                r0 += cs[t][u][0] + cs[t][u][1];
                r1 += cs[t][u][2] + cs[t][u][3];
            }
            r0 += __shfl_xor_sync(0xffffffffu, r0, 1);
            r0 += __shfl_xor_sync(0xffffffffu, r0, 2);
            r1 += __shfl_xor_sync(0xffffffffu, r1, 1);
            r1 += __shfl_xor_sync(0xffffffffu, r1, 2);
            if (tg == 0) {
                psum[(warp & 1) * 128 + wm + t * 16 + g]     = r0;
                psum[(warp & 1) * 128 + wm + t * 16 + g + 8] = r1;
            }
#pragma unroll
            for (int u = 0; u < 4; u++) {
                ph[t][u][0] = pkh2(cs[t][u][0], cs[t][u][1]);
                ph[t][u][1] = pkh2(cs[t][u][2], cs[t][u][3]);
                const int col = wn + u * 8 + 2 * tg;
                *(uint32_t*)&sP[(wm + t * 16 + g) * AST + col]     = ph[t][u][0];
                *(uint32_t*)&sP[(wm + t * 16 + g + 8) * AST + col] = ph[t][u][1];
            }
        }

#pragma unroll
        for (int c = 0; c < 2; c++) {
            const int kc = wn + 16 * c;
            uint32_t ap0[2][4];
#pragma unroll
            for (int t = 0; t < 2; t++) {
                ap0[t][0] = ph[t][2 * c][0];
                ap0[t][1] = ph[t][2 * c][1];
                ap0[t][2] = ph[t][2 * c + 1][0];
                ap0[t][3] = ph[t][2 * c + 1][1];
            }
#pragma unroll
            for (int u = 0; u < 4; u++) {
                const int d0 = wn + u * 8;
                const int vrow = kc + r8 + (sel & 1) * 8;
                uint32_t b0, b1;
                asm volatile("ldmatrix.sync.aligned.m8n8.x2.trans.shared.b16 {%0,%1}, [%2];"
                             : "=r"(b0), "=r"(b1) : "r"(s2u(&sV[vrow * AST + d0])));
#pragma unroll
                for (int t = 0; t < 2; t++)
                    mma4(cctx[t][u], ap0[t], b0, b1);
            }
        }
        __syncthreads();

        const int ko = wn ^ 32;
#pragma unroll
        for (int c = 0; c < 2; c++) {
            const int kc = ko + 16 * c;
            uint32_t ap[2][4];
#pragma unroll
            for (int t = 0; t < 2; t++)
                ldm_x4(ap[t], s2u(&sP[(wm + t * 16 + (sel & 1) * 8 + r8) * AST
                                      + kc + (sel >> 1) * 8]));
#pragma unroll
            for (int u = 0; u < 4; u++) {
                const int d0 = wn + u * 8;
                const int vrow = kc + r8 + (sel & 1) * 8;
                uint32_t b0, b1;
                asm volatile("ldmatrix.sync.aligned.m8n8.x2.trans.shared.b16 {%0,%1}, [%2];"
                             : "=r"(b0), "=r"(b1) : "r"(s2u(&sV[vrow * AST + d0])));
#pragma unroll
                for (int t = 0; t < 2; t++)
                    mma4(cctx[t][u], ap[t], b0, b1);
            }
        }

        if (tid < 128)
            sL[tid] += psum[tid] + psum[128 + tid];
    }
#undef AT_ISSUE
    __syncthreads();

#pragma unroll
    for (int t = 0; t < 2; t++) {
        const int r0 = wm + t * 16 + g;
        const float inv0 = 1.0f / sL[r0];
        const float inv1 = 1.0f / sL[r0 + 8];
#pragma unroll
        for (int u = 0; u < 4; u++) {
            const int cc = h * DK + wn + u * 8 + 2 * tg;
            float* c = cctx[t][u];
            float x0 = c[0] * inv0, x1 = c[1] * inv0;
            float x2 = c[2] * inv1, x3 = c[3] * inv1;
            __half h0, l0, h1, l1;
            size_t o0 = ((size_t)(q0 + r0) * BATCH + b) * DMODEL + cc;
            size_t o1 = ((size_t)(q0 + r0 + 8) * BATCH + b) * DMODEL + cc;
            split_h(x0, h0, l0); split_h(x1, h1, l1);
            *(__half2*)&g_Ch[o0] = __halves2half2(h0, h1);
            *(__half2*)&g_Cl[o0] = __halves2half2(l0, l1);
            split_h(x2, h0, l0); split_h(x3, h1, l1);
            *(__half2*)&g_Ch[o1] = __halves2half2(h0, h1);
            *(__half2*)&g_Cl[o1] = __halves2half2(l0, l1);
        }
    }
    if (tid < 128)
        g_L[(size_t)bh * S_LEN + q0 + tid] = sL[tid];
}

// ---------------------------------------------------------------------------
// Fused tail: blocks [0, 512) = output projection, [512, 2560) = attn_avg.
// ---------------------------------------------------------------------------
#define NOUTBLK 512

__global__ __launch_bounds__(256, 2) void tail_fused(
    const __half* __restrict__ Ch2, const __half* __restrict__ Cl2,
    const __half* __restrict__ woth,
    float* __restrict__ out, float* __restrict__ outA)
{
    extern __shared__ __align__(16) unsigned char smraw[];

    if (blockIdx.x < NOUTBLK) {
        const int bx = blockIdx.x & 7;        // n-tile (DMODEL/128 = 8)
        const int by = blockIdx.x >> 3;       // m-tile (ROWS/128 = 64)
        gemm_body<2, false, 3>(Ch2, Cl2, woth, out, nullptr, 1.0f,
                               ROWS, DMODEL, DMODEL, (__half*)smraw,
                               by * 128, bx * 128);
        return;
    }

    // ---- attn_avg part ----
    __half* sT  = (__half*)smraw;                 // [2][(128+64)][AST]: Q then K
    float* sInv = (float*)(smraw + (size_t)2 * 192 * AST * 2);  // [16][128]

    const int idx  = blockIdx.x - NOUTBLK;
    const int tid  = threadIdx.x;
    const int warp = tid >> 5;
    const int lane = tid & 31;
    const int g    = lane >> 2;
    const int tg   = lane & 3;
    const int r8   = lane & 7;
    const int sel  = lane >> 3;
    const int wm   = (warp >> 1) * 32;
    const int wn   = (warp & 1) * 32;

    const int j0 = (idx & 31) * 64;          // 32 j-tiles
    const int q0 = ((idx >> 5) & 15) * 128;  // 16 q-tiles
    const int b  = idx >> 9;                 // 4 batches

    for (int i = tid; i < NHEAD * 128; i += 256) {
        const int hh = i >> 7, qq = i & 127;
        sInv[i] = 1.0f / (16.0f * g_L[(size_t)(b * NHEAD + hh) * S_LEN + q0 + qq]);
    }

    const int qrow = tid >> 1;             // 0..127
    const int qcol = (tid & 1) * 32;
    const int krow = tid >> 2;             // 0..63
    const int kcol = (tid & 3) * 16;
    const uint32_t tb = s2u(sT);
    const uint32_t qoff = (uint32_t)(qrow * AST + qcol) * 2;
    const uint32_t koff = (uint32_t)((128 + krow) * AST + kcol) * 2;

#define AV_ISSUE(H, B)                                                         \
    {                                                                          \
        const uint32_t base = tb + (uint32_t)(B) * (192 * AST * 2);            \
        const __half* qp = g_Qh + ((size_t)(q0 + qrow) * BATCH + b) * DMODEL + (H) * DK + qcol; \
        cp16(base + qoff, qp);      cp16(base + qoff + 16, qp + 8);            \
        cp16(base + qoff + 32, qp + 16); cp16(base + qoff + 48, qp + 24);      \
        const __half* kp = g_Kh + ((size_t)(j0 + krow) * BATCH + b) * DMODEL + (H) * DK + kcol; \
        cp16(base + koff, kp);      cp16(base + koff + 16, kp + 8);            \
        CPC();                                                                 \
    }

    AV_ISSUE(0, 0)

    float avg[2][4][4] = {};

    for (int h = 0; h < NHEAD; h++) {
        const int cur = h & 1;
        __half* sQ = sT + cur * 192 * AST;
        __half* sK = sQ + 128 * AST;
        CPW0();
        __syncthreads();
        if (h + 1 < NHEAD) AV_ISSUE(h + 1, cur ^ 1)

        float cs[2][4][4] = {};
#pragma unroll
        for (int kc = 0; kc < 64; kc += 16) {
            uint32_t aq[2][4];
#pragma unroll
            for (int t = 0; t < 2; t++)
                ldm_x4(aq[t], s2u(&sQ[(wm + t * 16 + (sel & 1) * 8 + r8) * AST
                                      + kc + (sel >> 1) * 8]));
#pragma unroll
            for (int up = 0; up < 2; up++) {
                uint32_t bf[4];
                ldm_x4(bf, s2u(&sK[(wn + up * 16 + (sel >> 1) * 8 + r8) * AST
                                   + kc + (sel & 1) * 8]));
#pragma unroll
                for (int t = 0; t < 2; t++) {
                    mma4(cs[t][2 * up],     aq[t], bf[0], bf[1]);
                    mma4(cs[t][2 * up + 1], aq[t], bf[2], bf[3]);
                }
            }
        }

#pragma unroll
        for (int t = 0; t < 2; t++) {
            const float inv0 = sInv[h * 128 + wm + t * 16 + g];
            const float inv1 = sInv[h * 128 + wm + t * 16 + g + 8];
#pragma unroll
            for (int u = 0; u < 4; u++) {
                avg[t][u][0] += ex2f(cs[t][u][0]) * inv0;
                avg[t][u][1] += ex2f(cs[t][u][1]) * inv0;
                avg[t][u][2] += ex2f(cs[t][u][2]) * inv1;
                avg[t][u][3] += ex2f(cs[t][u][3]) * inv1;
            }
        }
    }
#undef AV_ISSUE

#pragma unroll
    for (int t = 0; t < 2; t++) {
        const int r0 = q0 + wm + t * 16 + g;
#pragma unroll
        for (int u = 0; u < 4; u++) {
            const int cc = j0 + wn + u * 8 + 2 * tg;
            float* c = avg[t][u];
            *(float2*)(outA + ((size_t)b * S_LEN + r0) * S_LEN + cc) =
                make_float2(c[0], c[1]);
            *(float2*)(outA + ((size_t)b * S_LEN + r0 + 8) * S_LEN + cc) =
                make_float2(c[2], c[3]);
        }
    }
}

// ---------------------------------------------------------------------------
// Launch
// ---------------------------------------------------------------------------
extern "C" void kernel_launch(void* const* d_in, const int* in_sizes, int n_in,
                              void* d_out, int out_size)
{
    (void)in_sizes; (void)n_in; (void)out_size;
    const float* query = (const float*)d_in[0];
    const float* key   = (const float*)d_in[1];
    const float* value = (const float*)d_in[2];
    const float* Wqk   = (const float*)d_in[3];
    const float* Wvot  = (const float*)d_in[4];

    float* out  = (float*)d_out;                              // (S,B,D)
    float* outA = out + (size_t)S_LEN * BATCH * DMODEL;       // (B,S,S)

    __half *qh, *ql, *kh, *kl, *vh, *vl;
    __half *wqkh, *wqkl, *wvh, *wvl, *woth, *wotl;
    __half *Qh, *Kh, *Vh, *pCh, *pCl;
    cudaGetSymbolAddress((void**)&qh,   g_qh);   cudaGetSymbolAddress((void**)&ql,   g_ql);
    cudaGetSymbolAddress((void**)&kh,   g_kh);   cudaGetSymbolAddress((void**)&kl,   g_kl);
    cudaGetSymbolAddress((void**)&vh,   g_vh);   cudaGetSymbolAddress((void**)&vl,   g_vl);
    cudaGetSymbolAddress((void**)&wqkh, g_wqkh); cudaGetSymbolAddress((void**)&wqkl, g_wqkl);
    cudaGetSymbolAddress((void**)&wvh,  g_wvh);  cudaGetSymbolAddress((void**)&wvl,  g_wvl);
    cudaGetSymbolAddress((void**)&woth, g_woth); cudaGetSymbolAddress((void**)&wotl, g_wotl);
    cudaGetSymbolAddress((void**)&Qh,   g_Qh);   cudaGetSymbolAddress((void**)&Kh,   g_Kh);
    cudaGetSymbolAddress((void**)&Vh,   g_Vh);
    cudaGetSymbolAddress((void**)&pCh,  g_Ch);   cudaGetSymbolAddress((void**)&pCl,  g_Cl);

    const int smem_g2 = 3 * 3 * ASZB;                            // 92160 B
    const int smem_at = 512 * AST * 2 + (256 + 128) * 4;         // 75264 B
    const int smem_tl = smem_g2;                                 // max(92160, 63488)
    cudaFuncSetAttribute(gemm_qkv,
                         cudaFuncAttributeMaxDynamicSharedMemorySize, smem_g2);
    cudaFuncSetAttribute(attn16,
                         cudaFuncAttributeMaxDynamicSharedMemorySize, smem_at);
    cudaFuncSetAttribute(tail_fused,
                         cudaFuncAttributeMaxDynamicSharedMemorySize, smem_tl);

    const int n4_act = ROWS * DMODEL / 4;
    const int n4_wqk = 2 * DMODEL * DMODEL / 4;
    const int n4_wv  = DMODEL * DMODEL / 4;

    split3<<<dim3((n4_act + 255) / 256, 1, 3), 256>>>(
        query, key, value, qh, ql, kh, kl, vh, vl, n4_act);
    split_w<<<dim3((n4_wqk + 255) / 256, 1, 2), 256>>>(
        Wqk, Wvot, wqkh, wqkl, wvh, wvl, n4_wqk, n4_wv);
    transpose_wo_split<<<dim3(32, 32), dim3(32, 8)>>>(Wvot);

    gemm_qkv<<<dim3(DMODEL / 128, ROWS / 128, 3), 256, smem_g2>>>(
        qh, ql, kh, vh, vl, wqkh, wvh, Qh, Kh, Vh);

    attn16<<<dim3(S_LEN / 128, BATCH * NHEAD), 256, smem_at>>>();

    tail_fused<<<NOUTBLK + S_LEN / 64 * S_LEN / 128 * BATCH, 256, smem_tl>>>(
        pCh, pCl, woth, out, outA);
}